// round 13
// baseline (speedup 1.0000x reference)
#include <cuda_runtime.h>

#define B_TOTAL 16384
#define H 128
#define NATT 3
#define NC 10
#define ROWS 32          // rows per block
#define NTHREADS 512
#define RPH 8            // rows per thread-group
#define PAD 132          // hs/us row stride: 16B-aligned, staggers banks
#define MOMPAD 20
#define LOG2E 1.4426950408889634f

// dynamic smem layout (floats)
#define WS_OFF   0                       // 128*128 = 16384
#define HS_OFF   16384                   // 32*132  = 4224
#define US_OFF   (HS_OFF + ROWS*PAD)     // 4224
#define MOM_OFF  (US_OFF + ROWS*PAD)     // 32*20 = 640
#define RED_OFF  (MOM_OFF + ROWS*MOMPAD) // 32*4 = 128
#define SMEM_FLOATS (RED_OFF + ROWS*4)
#define SMEM_BYTES  (SMEM_FLOATS * 4)    // 102,400 B -> 2 blocks/SM

typedef unsigned long long u64;

__device__ __forceinline__ float ex2f_(float x) {
    float y; asm("ex2.approx.f32 %0, %1;" : "=f"(y) : "f"(x)); return y;
}
__device__ __forceinline__ float rcpf_(float x) {
    float y; asm("rcp.approx.f32 %0, %1;" : "=f"(y) : "f"(x)); return y;
}
__device__ __forceinline__ float rsqrtf_(float x) {
    float y; asm("rsqrt.approx.f32 %0, %1;" : "=f"(y) : "f"(x)); return y;
}
__device__ __forceinline__ float tanh_acc(float x) {
    float e = ex2f_(2.0f * LOG2E * x);
    return 1.0f - 2.0f * rcpf_(e + 1.0f);
}

__device__ __forceinline__ u64 pack2_(float lo, float hi) {
    u64 r; asm("mov.b64 %0, {%1,%2};" : "=l"(r) : "f"(lo), "f"(hi)); return r;
}
__device__ __forceinline__ void unpack2_(u64 v, float& lo, float& hi) {
    asm("mov.b64 {%0,%1}, %2;" : "=f"(lo), "=f"(hi) : "l"(v));
}
__device__ __forceinline__ u64 fma2_(u64 a, u64 b, u64 c) {
    u64 r; asm("fma.rn.f32x2 %0, %1, %2, %3;" : "=l"(r) : "l"(a), "l"(b), "l"(c)); return r;
}

__constant__ float INV_FACT[9] = {
    1.0f, 1.0f, 0.5f, 1.6666666666666666e-1f, 4.1666666666666664e-2f,
    8.3333333333333332e-3f, 1.3888888888888889e-3f,
    1.9841269841269841e-4f, 2.4801587301587302e-5f
};

// Cooperative stage of 128x128 fp32 W into smem (linear, coalesced; 512 thr).
__device__ __forceinline__ void stage_w(float* __restrict__ Ws,
                                        const float* __restrict__ W, int tid)
{
    float4* d = (float4*)Ws;
    const float4* s = (const float4*)W;
    #pragma unroll
    for (int j = 0; j < 8; j++)
        d[tid + NTHREADS * j] = s[tid + NTHREADS * j];
}

// Matvec over 8 rows, W in smem: hout[r] = sum_k src[r0+r][k]*Ws[k*H+t] + bias
__device__ __forceinline__ void matvec8(const float* __restrict__ smem, int r0, int t,
                                        float bias, float* __restrict__ hout)
{
    const float (*src)[PAD] = (const float (*)[PAD])(smem + HS_OFF);
    const float* Ws = smem + WS_OFF;
    u64 acc[RPH];
    #pragma unroll
    for (int r = 0; r < RPH; r++) acc[r] = pack2_(0.f, 0.f);
    #pragma unroll 2
    for (int k = 0; k < H; k += 4) {
        float w0 = Ws[(k + 0) * H + t];
        float w1 = Ws[(k + 1) * H + t];
        float w2 = Ws[(k + 2) * H + t];
        float w3 = Ws[(k + 3) * H + t];
        u64 w01 = pack2_(w0, w1), w23 = pack2_(w2, w3);
        #pragma unroll
        for (int r = 0; r < RPH; r++) {
            ulonglong2 xv = *(const ulonglong2*)&src[r0 + r][k];
            acc[r] = fma2_(w01, xv.x, acc[r]);
            acc[r] = fma2_(w23, xv.y, acc[r]);
        }
    }
    #pragma unroll
    for (int r = 0; r < RPH; r++) {
        float lo, hi; unpack2_(acc[r], lo, hi);
        hout[r] = lo + hi + bias;
    }
}

__global__ __launch_bounds__(NTHREADS, 2)
void simpleattn_kernel(const float* __restrict__ x,
                       const float* __restrict__ W_in,
                       const float* __restrict__ b_in,
                       const float* __restrict__ W_att,
                       const float* __restrict__ b_att,
                       const float* __restrict__ gamma,
                       const float* __restrict__ beta,
                       const float* __restrict__ W_c,
                       const float* __restrict__ b_c,
                       float* __restrict__ out)
{
    extern __shared__ float smem[];
    float (*hs)[PAD]     = (float (*)[PAD])(smem + HS_OFF);
    float (*us)[PAD]     = (float (*)[PAD])(smem + US_OFF);
    float (*mom)[MOMPAD] = (float (*)[MOMPAD])(smem + MOM_OFF);
    float (*red)[4]      = (float (*)[4])(smem + RED_OFF);
    float* Ws            = smem + WS_OFF;

    const int tid  = threadIdx.x;
    const int t    = tid & 127;       // feature owned
    const int grp  = tid >> 7;        // 0..3 row groups
    const int r0   = grp * RPH;
    const int row0 = blockIdx.x * ROWS;
    const int rr   = tid >> 4;        // reduce-phase row (16 threads/row, 32 rows)
    const int j0   = (tid & 15) * 8;
    const int l16  = tid & 15;

    // ---- stage W_in + x tile ----
    stage_w(Ws, W_in, tid);
    #pragma unroll
    for (int r = 0; r < RPH; r++)
        hs[r0 + r][t] = x[(row0 + r0 + r) * H + t];
    __syncthreads();

    // ---- in_proj: h = x @ W_in + b_in ----
    float h[RPH];
    matvec8(smem, r0, t, b_in[t], h);
    __syncthreads();                  // x reads + W_in reads done
    #pragma unroll
    for (int r = 0; r < RPH; r++) hs[r0 + r][t] = h[r];
    stage_w(Ws, W_att, tid);          // layer 0 weights
    __syncthreads();

    // ---- attention layers ----
    float u[RPH], y[RPH];
    for (int layer = 0; layer < NATT; layer++) {
        // u = tanh(h @ W_att[layer] + b_att[layer])
        matvec8(smem, r0, t, b_att[layer * H + t], u);
        #pragma unroll
        for (int r = 0; r < RPH; r++) {
            u[r] = tanh_acc(u[r]);
            us[r0 + r][t] = u[r];
        }
        __syncthreads();              // matvec Ws reads complete; us visible

        // prefetch next layer's W into the now-dead Ws buffer; latency
        // hides under the moment/eval/LN phases below.
        if (layer < NATT - 1)
            stage_w(Ws, W_att + (layer + 1) * H * H, tid);

        // ---- moments: S_n = sum_j u^n h (n=0..8), T_n = sum_j u^n (n=1..8)
        {
            float S[9], T8[8];
            #pragma unroll
            for (int i = 0; i < 9; i++) S[i] = 0.f;
            #pragma unroll
            for (int i = 0; i < 8; i++) T8[i] = 0.f;
            #pragma unroll
            for (int jj = 0; jj < 8; jj += 4) {
                float4 uv = *(const float4*)&us[rr][j0 + jj];
                float4 hv = *(const float4*)&hs[rr][j0 + jj];
                #pragma unroll
                for (int c = 0; c < 4; c++) {
                    float p  = (c == 0) ? uv.x : (c == 1) ? uv.y : (c == 2) ? uv.z : uv.w;
                    float hh = (c == 0) ? hv.x : (c == 1) ? hv.y : (c == 2) ? hv.z : hv.w;
                    S[0] += hh;
                    float pw = p;
                    S[1] += pw * hh; T8[0] += pw;
                    #pragma unroll
                    for (int n = 2; n <= 8; n++) {
                        pw *= p;
                        S[n] += pw * hh;
                        T8[n - 1] += pw;
                    }
                }
            }
            #pragma unroll
            for (int o = 8; o >= 1; o >>= 1) {
                #pragma unroll
                for (int i = 0; i < 9; i++) S[i]  += __shfl_xor_sync(0xffffffffu, S[i], o);
                #pragma unroll
                for (int i = 0; i < 8; i++) T8[i] += __shfl_xor_sync(0xffffffffu, T8[i], o);
            }
            if (l16 == 0) {
                #pragma unroll
                for (int i = 0; i < 9; i++)  mom[rr][i]      = S[i]  * INV_FACT[i];
                #pragma unroll
                for (int i = 1; i <= 8; i++) mom[rr][11 + i] = T8[i - 1] * INV_FACT[i];
            }
        }
        __syncthreads();

        // ---- eval: Horner over the rank-9 expansion; write y into us ----
        #pragma unroll
        for (int r = 0; r < RPH; r++) {
            const float* m = mom[r0 + r];
            float4 a0 = *(const float4*)&m[0];
            float4 a1 = *(const float4*)&m[4];
            float  m8 = m[8];
            float4 t0 = *(const float4*)&m[12];
            float4 t1 = *(const float4*)&m[16];
            float p = u[r];
            float num = m8;
            num = num * p + a1.w;  num = num * p + a1.z;
            num = num * p + a1.y;  num = num * p + a1.x;
            num = num * p + a0.w;  num = num * p + a0.z;
            num = num * p + a0.y;  num = num * p + a0.x;
            float den = t1.w;
            den = den * p + t1.z;  den = den * p + t1.y;
            den = den * p + t1.x;  den = den * p + t0.w;
            den = den * p + t0.z;  den = den * p + t0.y;
            den = den * p + t0.x;  den = den * p + (float)H;
            y[r] = h[r] + num * rcpf_(den);
            us[r0 + r][t] = y[r];
        }
        __syncthreads();

        // ---- LN reduce: 16 threads/row; lane0 writes mean, inv-std ----
        {
            float s = 0.f, q = 0.f;
            #pragma unroll
            for (int jj = 0; jj < 8; jj += 4) {
                float4 yv = *(const float4*)&us[rr][j0 + jj];
                s += (yv.x + yv.y) + (yv.z + yv.w);
                q += (yv.x * yv.x + yv.y * yv.y) + (yv.z * yv.z + yv.w * yv.w);
            }
            #pragma unroll
            for (int o = 8; o >= 1; o >>= 1) {
                s += __shfl_xor_sync(0xffffffffu, s, o);
                q += __shfl_xor_sync(0xffffffffu, q, o);
            }
            if (l16 == 0) {
                float m   = s * (1.0f / H);
                float var = q * (1.0f / H) - m * m;
                red[rr][0] = m;
                red[rr][1] = rsqrtf_(var + 1e-5f);
            }
        }
        __syncthreads();

        // ---- normalize ----
        float g  = gamma[layer * H + t];
        float bt = beta[layer * H + t];
        #pragma unroll
        for (int r = 0; r < RPH; r++) {
            float m   = red[r0 + r][0];
            float inv = red[r0 + r][1];
            h[r] = (y[r] - m) * inv * g + bt;
            hs[r0 + r][t] = h[r];
        }
        __syncthreads();              // hs + staged Ws visible for next matvec
    }

    // ---- classifier: out = h @ W_c + b_c ----
    if (tid < ROWS * NC) {
        int r = tid / NC, c = tid - r * NC;
        float acc = b_c[c];
        #pragma unroll 8
        for (int k = 0; k < H; k++)
            acc += hs[r][k] * W_c[k * NC + c];
        out[(row0 + r) * NC + c] = acc;
    }
}

extern "C" void kernel_launch(void* const* d_in, const int* in_sizes, int n_in,
                              void* d_out, int out_size)
{
    const float* x     = (const float*)d_in[0];
    const float* W_in  = (const float*)d_in[1];
    const float* b_in  = (const float*)d_in[2];
    const float* W_att = (const float*)d_in[3];
    const float* b_att = (const float*)d_in[4];
    const float* gamma = (const float*)d_in[5];
    const float* beta  = (const float*)d_in[6];
    const float* W_c   = (const float*)d_in[7];
    const float* b_c   = (const float*)d_in[8];
    float* out = (float*)d_out;

    static int smem_set = 0;
    if (!smem_set) {
        cudaFuncSetAttribute(simpleattn_kernel,
                             cudaFuncAttributeMaxDynamicSharedMemorySize, SMEM_BYTES);
        smem_set = 1;
    }
    dim3 grid(B_TOTAL / ROWS);   // 512 blocks
    dim3 block(NTHREADS);        // 512 threads
    simpleattn_kernel<<<grid, block, SMEM_BYTES>>>(x, W_in, b_in, W_att, b_att,
                                                   gamma, beta, W_c, b_c, out);
}

// round 15
// speedup vs baseline: 1.2386x; 1.2386x over previous
#include <cuda_runtime.h>

#define B_TOTAL 16384
#define H 128
#define NATT 3
#define NC 10
#define ROWS 16          // rows per block
#define RPH 8            // rows per half-block
#define PAD 132          // row stride: 16B-aligned, staggers banks
#define MOMPAD 20        // moment row stride: S at [0..8], T at [12..19]
#define LOG2E 1.4426950408889634f

typedef unsigned long long u64;

__device__ __forceinline__ float ex2f_(float x) {
    float y; asm("ex2.approx.f32 %0, %1;" : "=f"(y) : "f"(x)); return y;
}
__device__ __forceinline__ float rcpf_(float x) {
    float y; asm("rcp.approx.f32 %0, %1;" : "=f"(y) : "f"(x)); return y;
}
__device__ __forceinline__ float rsqrtf_(float x) {
    float y; asm("rsqrt.approx.f32 %0, %1;" : "=f"(y) : "f"(x)); return y;
}
// Accurate tanh: 1 - 2/(e^{2x}+1); ex2/rcp approx ~2^-22 rel err.
__device__ __forceinline__ float tanh_acc(float x) {
    float e = ex2f_(2.0f * LOG2E * x);
    return 1.0f - 2.0f * rcpf_(e + 1.0f);
}

// ---- packed f32x2 helpers (sm_103a) ----
__device__ __forceinline__ u64 pack2_(float lo, float hi) {
    u64 r; asm("mov.b64 %0, {%1,%2};" : "=l"(r) : "f"(lo), "f"(hi)); return r;
}
__device__ __forceinline__ void unpack2_(u64 v, float& lo, float& hi) {
    asm("mov.b64 {%0,%1}, %2;" : "=f"(lo), "=f"(hi) : "l"(v));
}
__device__ __forceinline__ u64 fma2_(u64 a, u64 b, u64 c) {
    u64 r; asm("fma.rn.f32x2 %0, %1, %2, %3;" : "=l"(r) : "l"(a), "l"(b), "l"(c)); return r;
}

__constant__ float INV_FACT[9] = {
    1.0f, 1.0f, 0.5f, 1.6666666666666666e-1f, 4.1666666666666664e-2f,
    8.3333333333333332e-3f, 1.3888888888888889e-3f,
    1.9841269841269841e-4f, 2.4801587301587302e-5f
};

// Packed matvec over 8 rows: hout[r] = sum_k src[r0+r][k] * W[k*H + t] + bias
__device__ __forceinline__ void matvec8(const float (*__restrict__ src)[PAD], int r0, int t,
                                        const float* __restrict__ W,
                                        float bias, float* __restrict__ hout)
{
    u64 acc[RPH];
    #pragma unroll
    for (int r = 0; r < RPH; r++) acc[r] = pack2_(0.f, 0.f);
    #pragma unroll 2
    for (int k = 0; k < H; k += 4) {
        float w0 = W[(k + 0) * H + t];
        float w1 = W[(k + 1) * H + t];
        float w2 = W[(k + 2) * H + t];
        float w3 = W[(k + 3) * H + t];
        u64 w01 = pack2_(w0, w1), w23 = pack2_(w2, w3);
        #pragma unroll
        for (int r = 0; r < RPH; r++) {
            ulonglong2 xv = *(const ulonglong2*)&src[r0 + r][k];
            acc[r] = fma2_(w01, xv.x, acc[r]);
            acc[r] = fma2_(w23, xv.y, acc[r]);
        }
    }
    #pragma unroll
    for (int r = 0; r < RPH; r++) {
        float lo, hi; unpack2_(acc[r], lo, hi);
        hout[r] = lo + hi + bias;
    }
}

__global__ __launch_bounds__(256, 4)
void simpleattn_kernel(const float* __restrict__ x,
                       const float* __restrict__ W_in,
                       const float* __restrict__ b_in,
                       const float* __restrict__ W_att,
                       const float* __restrict__ b_att,
                       const float* __restrict__ gamma,
                       const float* __restrict__ beta,
                       const float* __restrict__ W_c,
                       const float* __restrict__ b_c,
                       float* __restrict__ out)
{
    __shared__ float hs[ROWS][PAD];      // hidden state (also x staging)
    __shared__ float us[ROWS][PAD];      // u values, then y values
    __shared__ float mom[ROWS][MOMPAD];  // scaled moments
    __shared__ float red[ROWS][4];       // LN: [0]=mean, [1]=inv-std

    const int tid  = threadIdx.x;
    const int t    = tid & 127;       // feature owned (matvec/eval/normalize)
    const int half = tid >> 7;
    const int r0   = half * RPH;
    const int row0 = blockIdx.x * ROWS;
    const int rr   = tid >> 4;        // reduce-phase row (16 threads/row)
    const int j0   = (tid & 15) * 8;  // reduce-phase feature chunk
    const int l16  = tid & 15;

    // ---- stage x tile into hs ----
    #pragma unroll
    for (int r = 0; r < RPH; r++)
        hs[r0 + r][t] = x[(row0 + r0 + r) * H + t];
    __syncthreads();

    // ---- in_proj: h = x @ W_in + b_in ----
    float h[RPH];
    matvec8(hs, r0, t, W_in, b_in[t], h);
    __syncthreads();                  // all x reads done before overwrite
    #pragma unroll
    for (int r = 0; r < RPH; r++) hs[r0 + r][t] = h[r];
    __syncthreads();

    // ---- attention layers ----
    for (int layer = 0; layer < NATT; layer++) {
        const float* Wl = W_att + layer * H * H;

        // u = tanh(h @ Wl + b_att[layer]); u lives in us (re-read later,
        // keeps register count under the 64-reg occ-4 budget)
        {
            float uv[RPH];
            matvec8(hs, r0, t, Wl, b_att[layer * H + t], uv);
            #pragma unroll
            for (int r = 0; r < RPH; r++)
                us[r0 + r][t] = tanh_acc(uv[r]);
        }
        __syncthreads();

        // ---- moments: S_n = sum_j u^n h (n=0..8), T_n = sum_j u^n (n=1..8)
        // 16 threads/row, local accumulation over 8 j's, 4-stage butterfly.
        {
            float S[9], T8[8];
            #pragma unroll
            for (int i = 0; i < 9; i++) S[i] = 0.f;
            #pragma unroll
            for (int i = 0; i < 8; i++) T8[i] = 0.f;
            #pragma unroll
            for (int jj = 0; jj < 8; jj += 4) {
                float4 uv = *(const float4*)&us[rr][j0 + jj];
                float4 hv = *(const float4*)&hs[rr][j0 + jj];
                #pragma unroll
                for (int c = 0; c < 4; c++) {
                    float p  = (c == 0) ? uv.x : (c == 1) ? uv.y : (c == 2) ? uv.z : uv.w;
                    float hh = (c == 0) ? hv.x : (c == 1) ? hv.y : (c == 2) ? hv.z : hv.w;
                    S[0] += hh;
                    float pw = p;
                    S[1] += pw * hh; T8[0] += pw;
                    #pragma unroll
                    for (int n = 2; n <= 8; n++) {
                        pw *= p;
                        S[n] += pw * hh;
                        T8[n - 1] += pw;
                    }
                }
            }
            #pragma unroll
            for (int o = 8; o >= 1; o >>= 1) {
                #pragma unroll
                for (int i = 0; i < 9; i++) S[i]  += __shfl_xor_sync(0xffffffffu, S[i], o);
                #pragma unroll
                for (int i = 0; i < 8; i++) T8[i] += __shfl_xor_sync(0xffffffffu, T8[i], o);
            }
            if (l16 == 0) {
                #pragma unroll
                for (int i = 0; i < 9; i++)  mom[rr][i]      = S[i]  * INV_FACT[i];
                #pragma unroll
                for (int i = 1; i <= 8; i++) mom[rr][11 + i] = T8[i - 1] * INV_FACT[i];
            }
        }
        __syncthreads();

        // ---- eval: Horner over the rank-9 expansion; y overwrites u in us ----
        #pragma unroll
        for (int r = 0; r < RPH; r++) {
            const float* m = mom[r0 + r];
            float4 a0 = *(const float4*)&m[0];
            float4 a1 = *(const float4*)&m[4];
            float  m8 = m[8];
            float4 t0 = *(const float4*)&m[12];
            float4 t1 = *(const float4*)&m[16];
            float p = us[r0 + r][t];          // u re-read (register diet)
            float num = m8;
            num = num * p + a1.w;  num = num * p + a1.z;
            num = num * p + a1.y;  num = num * p + a1.x;
            num = num * p + a0.w;  num = num * p + a0.z;
            num = num * p + a0.y;  num = num * p + a0.x;
            float den = t1.w;
            den = den * p + t1.z;  den = den * p + t1.y;
            den = den * p + t1.x;  den = den * p + t0.w;
            den = den * p + t0.z;  den = den * p + t0.y;
            den = den * p + t0.x;  den = den * p + (float)H;
            us[r0 + r][t] = h[r] + num * rcpf_(den);   // y (residual)
        }
        __syncthreads();   // every thread reads only its own us element above,
                           // then all y's must be visible for LN reduce

        // ---- LN reduce: 16 threads/row on us(=y); lane0 writes mean, inv ----
        {
            float s = 0.f, q = 0.f;
            #pragma unroll
            for (int jj = 0; jj < 8; jj += 4) {
                float4 yv = *(const float4*)&us[rr][j0 + jj];
                s += (yv.x + yv.y) + (yv.z + yv.w);
                q += (yv.x * yv.x + yv.y * yv.y) + (yv.z * yv.z + yv.w * yv.w);
            }
            #pragma unroll
            for (int o = 8; o >= 1; o >>= 1) {
                s += __shfl_xor_sync(0xffffffffu, s, o);
                q += __shfl_xor_sync(0xffffffffu, q, o);
            }
            if (l16 == 0) {
                float m   = s * (1.0f / H);
                float var = q * (1.0f / H) - m * m;
                red[rr][0] = m;
                red[rr][1] = rsqrtf_(var + 1e-5f);
            }
        }
        __syncthreads();

        // ---- normalize (y re-read from us) ----
        float g  = gamma[layer * H + t];
        float bt = beta[layer * H + t];
        #pragma unroll
        for (int r = 0; r < RPH; r++) {
            float yv  = us[r0 + r][t];
            float m   = red[r0 + r][0];
            float inv = red[r0 + r][1];
            h[r] = (yv - m) * inv * g + bt;
            hs[r0 + r][t] = h[r];
        }
        __syncthreads();
    }

    // ---- classifier: out = h @ W_c + b_c ----
    if (tid < ROWS * NC) {
        int r = tid / NC, c = tid - r * NC;
        float acc = b_c[c];
        #pragma unroll 8
        for (int k = 0; k < H; k++)
            acc += hs[r][k] * W_c[k * NC + c];
        out[(row0 + r) * NC + c] = acc;
    }
}

extern "C" void kernel_launch(void* const* d_in, const int* in_sizes, int n_in,
                              void* d_out, int out_size)
{
    const float* x     = (const float*)d_in[0];
    const float* W_in  = (const float*)d_in[1];
    const float* b_in  = (const float*)d_in[2];
    const float* W_att = (const float*)d_in[3];
    const float* b_att = (const float*)d_in[4];
    const float* gamma = (const float*)d_in[5];
    const float* beta  = (const float*)d_in[6];
    const float* W_c   = (const float*)d_in[7];
    const float* b_c   = (const float*)d_in[8];
    float* out = (float*)d_out;

    dim3 grid(B_TOTAL / ROWS);   // 1024 blocks
    dim3 block(256);
    simpleattn_kernel<<<grid, block>>>(x, W_in, b_in, W_att, b_att,
                                       gamma, beta, W_c, b_c, out);
}